// round 1
// baseline (speedup 1.0000x reference)
#include <cuda_runtime.h>
#include <cuda_bf16.h>
#include <mma.h>
#include <type_traits>

using namespace nvcuda;

// Problem shape (fixed by dataset)
#define NROWS 8192
#define DIN   512
#define H1W   256
#define H2W   128
#define NSTEP 5
#define N1 (NSTEP*H1W)   // 1280 (concat of 5 step slabs of 256)
#define N2 (NSTEP*H2W)   // 640  (concat of 5 step slabs of 128)

// Tiling
#define BM 128
#define BN 128
#define BK 32
#define ALD (BK+8)   // 40
#define BLD (BN+8)   // 136

// ---------------------------------------------------------------------------
// Scratch (device globals — no runtime allocation allowed)
// ---------------------------------------------------------------------------
__device__ __nv_bfloat16 g_adjb[(size_t)NROWS*NROWS];   // adj in bf16 (134 MB)
__device__ float         g_T1 [(size_t)NROWS*N1];       // X@W1 slabs      (40 MB)
__device__ float         g_H1 [(size_t)NROWS*N1];       // relu(adj@T1)    (40 MB)
__device__ float         g_T2 [(size_t)NROWS*N2];       // H1@W2 slabs     (20 MB)
__device__ float         g_H2 [(size_t)NROWS*N2];       // relu(adj@T2)    (20 MB)
__device__ __nv_bfloat16 g_abf[(size_t)NROWS*N2];       // centered a bf16 (10 MB)
__device__ float         g_mean[N2];

// ---------------------------------------------------------------------------
// Helpers
// ---------------------------------------------------------------------------
static __device__ __forceinline__ void st4bf(__nv_bfloat16* p, float4 v) {
    __nv_bfloat162* q = reinterpret_cast<__nv_bfloat162*>(p);
    q[0] = __floats2bfloat162_rn(v.x, v.y);
    q[1] = __floats2bfloat162_rn(v.z, v.w);
}

// Hybrid sigmoid: Taylor for |x|<0.25 (abs err < 2e-8), exact MUFU path otherwise.
// Warp-voted so the MUFU path is skipped entirely when no lane needs it.
static __device__ __forceinline__ float fast_sigmoid(float x) {
    float ax = fabsf(x);
    float x2 = x * x;
    float p = 0.5f + x * (0.25f + x2 * (-0.0208333333f + x2 * 0.00208333333f));
    unsigned vote = __ballot_sync(0xFFFFFFFFu, ax >= 0.25f);
    if (vote) {
        if (ax >= 0.25f) p = __fdividef(1.0f, 1.0f + __expf(-x));
    }
    return p;
}

// ---------------------------------------------------------------------------
// fp32 -> bf16 bulk convert (adj)
// ---------------------------------------------------------------------------
__global__ void cvt_bf16_kernel(const float* __restrict__ src,
                                __nv_bfloat16* __restrict__ dst, long n4) {
    long i = (long)blockIdx.x * blockDim.x + threadIdx.x;
    long stride = (long)gridDim.x * blockDim.x;
    for (; i < n4; i += stride) {
        float4 v = reinterpret_cast<const float4*>(src)[i];
        st4bf(dst + i * 4, v);
    }
}

// ---------------------------------------------------------------------------
// Generic WMMA bf16 GEMM, fp32 accumulate, fp32 output, optional relu.
// A is bf16 or fp32 (converted on load). B is fp32 (converted on load) and may
// be "slabbed": output column block n in [s*outSlab, (s+1)*outSlab) uses
//   B + s*bSlabStride  and A column offset s*aSlabColStride.
// BN=128 divides every slab width used, so slab is block-uniform.
// ---------------------------------------------------------------------------
template <typename AT>
__global__ void __launch_bounds__(256)
gemm_kernel(const AT* __restrict__ A, int lda, int aSlabColStride,
            const float* __restrict__ B, int ldb, long bSlabStride, int outSlab,
            float* __restrict__ C, int ldc, int K, int doRelu) {
    __shared__ __nv_bfloat16 As[BM][ALD];
    __shared__ __nv_bfloat16 Bs[BK][BLD];

    const int bx = blockIdx.x, by = blockIdx.y;
    const int tid = threadIdx.x;
    const int slab = (bx * BN) / outSlab;
    const int jin0 = (bx * BN) % outSlab;
    const float* Bp = B + (long)slab * bSlabStride + jin0;
    const AT* Ap = A + (long)(by * BM) * lda + (long)slab * aSlabColStride;

    const int warp = tid >> 5;
    const int wm = warp >> 1;     // 0..3 (32-row stripes)
    const int wn = warp & 1;      // 0..1 (64-col stripes)

    wmma::fragment<wmma::accumulator, 16, 16, 16, float> cf[2][4];
    #pragma unroll
    for (int i = 0; i < 2; i++)
        #pragma unroll
        for (int j = 0; j < 4; j++) wmma::fill_fragment(cf[i][j], 0.0f);

    for (int kc = 0; kc < K; kc += BK) {
        // ---- stage A tile (BM x BK) ----
        if constexpr (std::is_same<AT, __nv_bfloat16>::value) {
            const int cvec = (tid & 3) * 8;
            const int row0 = tid >> 2;
            #pragma unroll
            for (int p = 0; p < 2; p++) {
                int r = row0 + p * 64;
                uint4 v = *reinterpret_cast<const uint4*>(Ap + (long)r * lda + kc + cvec);
                *reinterpret_cast<uint4*>(&As[r][cvec]) = v;
            }
        } else {
            const int cvec = (tid & 7) * 4;
            const int row0 = tid >> 3;
            #pragma unroll
            for (int p = 0; p < 4; p++) {
                int r = row0 + p * 32;
                float4 v = *reinterpret_cast<const float4*>(Ap + (long)r * lda + kc + cvec);
                st4bf(&As[r][cvec], v);
            }
        }
        // ---- stage B tile (BK x BN), fp32 -> bf16 ----
        {
            const int cvec = (tid & 31) * 4;
            const int row0 = tid >> 5;
            #pragma unroll
            for (int p = 0; p < 4; p++) {
                int r = row0 + p * 8;
                float4 v = *reinterpret_cast<const float4*>(Bp + (long)(kc + r) * ldb + cvec);
                st4bf(&Bs[r][cvec], v);
            }
        }
        __syncthreads();

        #pragma unroll
        for (int kk = 0; kk < BK; kk += 16) {
            wmma::fragment<wmma::matrix_a, 16, 16, 16, __nv_bfloat16, wmma::row_major> af[2];
            wmma::fragment<wmma::matrix_b, 16, 16, 16, __nv_bfloat16, wmma::row_major> bfr[4];
            #pragma unroll
            for (int i = 0; i < 2; i++)
                wmma::load_matrix_sync(af[i], &As[wm * 32 + i * 16][kk], ALD);
            #pragma unroll
            for (int j = 0; j < 4; j++)
                wmma::load_matrix_sync(bfr[j], &Bs[kk][wn * 64 + j * 16], BLD);
            #pragma unroll
            for (int i = 0; i < 2; i++)
                #pragma unroll
                for (int j = 0; j < 4; j++)
                    wmma::mma_sync(cf[i][j], af[i], bfr[j], cf[i][j]);
        }
        __syncthreads();
    }

    #pragma unroll
    for (int i = 0; i < 2; i++)
        #pragma unroll
        for (int j = 0; j < 4; j++) {
            if (doRelu) {
                #pragma unroll
                for (int e = 0; e < cf[i][j].num_elements; e++)
                    cf[i][j].x[e] = fmaxf(cf[i][j].x[e], 0.0f);
            }
            float* Cp = C + (long)(by * BM + wm * 32 + i * 16) * ldc
                          + (long)bx * BN + wn * 64 + j * 16;
            wmma::store_matrix_sync(Cp, cf[i][j], ldc, wmma::mem_row_major);
        }
}

// ---------------------------------------------------------------------------
// Column means of H2 (8192 x 640)
// ---------------------------------------------------------------------------
__global__ void mean_kernel(const float* __restrict__ H2, float* __restrict__ mean) {
    const int tx = threadIdx.x & 31;
    const int ty = threadIdx.x >> 5;   // 0..7
    const int col = blockIdx.x * 32 + tx;
    float s = 0.0f;
    for (int r = ty; r < NROWS; r += 8)
        s += H2[(long)r * N2 + col];
    __shared__ float red[8][32];
    red[ty][tx] = s;
    __syncthreads();
    if (ty == 0) {
        float t = 0.0f;
        #pragma unroll
        for (int i = 0; i < 8; i++) t += red[i][tx];
        mean[col] = t * (1.0f / NROWS);
    }
}

// a = bf16(H2 - colmean)
__global__ void center_kernel(const float* __restrict__ H2,
                              const float* __restrict__ mean,
                              __nv_bfloat16* __restrict__ a, long n) {
    long i = (long)blockIdx.x * blockDim.x + threadIdx.x;
    long st = (long)gridDim.x * blockDim.x;
    for (; i < n; i += st) {
        int c = (int)(i % N2);
        a[i] = __float2bfloat16(H2[i] - mean[c]);
    }
}

// ---------------------------------------------------------------------------
// Fused output kernel: out[r,c] = (sum over active steps q of
//     sqrt_omac[q] * sigmoid( dot(a_q[r,:], a_q[c,:]) )) / cum_sqrt[ts-1]
// K=128 per step, 5 steps, output written exactly once.
// ---------------------------------------------------------------------------
__global__ void __launch_bounds__(256)
out_kernel(const __nv_bfloat16* __restrict__ a,
           const float* __restrict__ sqrt_omac,
           const float* __restrict__ cum_sqrt,
           const int* __restrict__ tsp, const int* __restrict__ Tp,
           float* __restrict__ out) {
    __shared__ __nv_bfloat16 As[BM][ALD];   // row-side tile  [m][k]
    __shared__ __nv_bfloat16 Bs[BM][ALD];   // col-side tile  [n][k]

    const int ts = *tsp, T = *Tp;
    const int bx = blockIdx.x, by = blockIdx.y;
    const int tid = threadIdx.x;
    const int warp = tid >> 5;
    const int wm = warp >> 1, wn = warp & 1;

    wmma::fragment<wmma::accumulator, 16, 16, 16, float> of[2][4];
    #pragma unroll
    for (int i = 0; i < 2; i++)
        #pragma unroll
        for (int j = 0; j < 4; j++) wmma::fill_fragment(of[i][j], 0.0f);

    const int cvec = (tid & 3) * 8;
    const int row0 = tid >> 2;

    for (int q = 0; q < NSTEP; q++) {
        const int stepAbs = q + 1;
        if (stepAbs < ts || stepAbs > T) continue;   // uniform over grid
        const float coef = sqrt_omac[q];             // sqrt_omac[s-1]

        wmma::fragment<wmma::accumulator, 16, 16, 16, float> cf[2][4];
        #pragma unroll
        for (int i = 0; i < 2; i++)
            #pragma unroll
            for (int j = 0; j < 4; j++) wmma::fill_fragment(cf[i][j], 0.0f);

        for (int kc = 0; kc < H2W; kc += BK) {
            #pragma unroll
            for (int p = 0; p < 2; p++) {
                int r = row0 + p * 64;
                uint4 va = *reinterpret_cast<const uint4*>(
                    a + (long)(by * BM + r) * N2 + q * H2W + kc + cvec);
                *reinterpret_cast<uint4*>(&As[r][cvec]) = va;
                uint4 vb = *reinterpret_cast<const uint4*>(
                    a + (long)(bx * BM + r) * N2 + q * H2W + kc + cvec);
                *reinterpret_cast<uint4*>(&Bs[r][cvec]) = vb;
            }
            __syncthreads();

            #pragma unroll
            for (int kk = 0; kk < BK; kk += 16) {
                wmma::fragment<wmma::matrix_a, 16, 16, 16, __nv_bfloat16, wmma::row_major> af[2];
                wmma::fragment<wmma::matrix_b, 16, 16, 16, __nv_bfloat16, wmma::col_major> bfr[4];
                #pragma unroll
                for (int i = 0; i < 2; i++)
                    wmma::load_matrix_sync(af[i], &As[wm * 32 + i * 16][kk], ALD);
                #pragma unroll
                for (int j = 0; j < 4; j++)   // col_major: (k,n) -> Bs[n][k]
                    wmma::load_matrix_sync(bfr[j], &Bs[wn * 64 + j * 16][kk], ALD);
                #pragma unroll
                for (int i = 0; i < 2; i++)
                    #pragma unroll
                    for (int j = 0; j < 4; j++)
                        wmma::mma_sync(cf[i][j], af[i], bfr[j], cf[i][j]);
            }
            __syncthreads();
        }

        #pragma unroll
        for (int i = 0; i < 2; i++)
            #pragma unroll
            for (int j = 0; j < 4; j++)
                #pragma unroll
                for (int e = 0; e < cf[i][j].num_elements; e++)
                    of[i][j].x[e] += coef * fast_sigmoid(cf[i][j].x[e]);
    }

    const float inv = __fdividef(1.0f, cum_sqrt[ts - 1]);
    #pragma unroll
    for (int i = 0; i < 2; i++)
        #pragma unroll
        for (int j = 0; j < 4; j++) {
            #pragma unroll
            for (int e = 0; e < of[i][j].num_elements; e++)
                of[i][j].x[e] *= inv;
            float* Cp = out + (long)(by * BM + wm * 32 + i * 16) * NROWS
                            + (long)bx * BM + wn * 64 + j * 16;
            wmma::store_matrix_sync(Cp, of[i][j], NROWS, wmma::mem_row_major);
        }
}

// ---------------------------------------------------------------------------
// Launch: phase 1 computes all 5 step slabs unconditionally (deterministic,
// graph-static); step gating via device-side time_step/timesteps happens only
// in out_kernel, matching reference semantics for any 1<=time_step<=timesteps<=5.
// ---------------------------------------------------------------------------
extern "C" void kernel_launch(void* const* d_in, const int* in_sizes, int n_in,
                              void* d_out, int out_size) {
    const float* X   = (const float*)d_in[0];
    const float* adj = (const float*)d_in[1];
    const float* W1  = (const float*)d_in[2];
    const float* W2  = (const float*)d_in[3];
    const float* cum = (const float*)d_in[4];
    const float* som = (const float*)d_in[5];
    const int*   tsp = (const int*)d_in[6];
    const int*   Tp  = (const int*)d_in[7];
    float* out = (float*)d_out;
    (void)in_sizes; (void)n_in; (void)out_size;

    void *p_adjb, *p_t1, *p_h1, *p_t2, *p_h2, *p_abf, *p_mean;
    cudaGetSymbolAddress(&p_adjb, g_adjb);
    cudaGetSymbolAddress(&p_t1, g_T1);
    cudaGetSymbolAddress(&p_h1, g_H1);
    cudaGetSymbolAddress(&p_t2, g_T2);
    cudaGetSymbolAddress(&p_h2, g_H2);
    cudaGetSymbolAddress(&p_abf, g_abf);
    cudaGetSymbolAddress(&p_mean, g_mean);

    // adj -> bf16 once
    cvt_bf16_kernel<<<4096, 256>>>(adj, (__nv_bfloat16*)p_adjb,
                                   (long)NROWS * NROWS / 4);

    // T1[:, q*256:(q+1)*256] = X @ W1[q+1]
    gemm_kernel<float><<<dim3(N1 / BN, NROWS / BM), 256>>>(
        X, DIN, 0,
        W1 + (size_t)DIN * H1W, H1W, (long)DIN * H1W, H1W,
        (float*)p_t1, N1, DIN, 0);

    // H1 = relu(adj @ T1)   (all 5 slabs in one GEMM, adj read once)
    gemm_kernel<__nv_bfloat16><<<dim3(N1 / BN, NROWS / BM), 256>>>(
        (const __nv_bfloat16*)p_adjb, NROWS, 0,
        (const float*)p_t1, N1, 0, N1,
        (float*)p_h1, N1, NROWS, 1);

    // T2[:, q*128:(q+1)*128] = H1[:, q*256:(q+1)*256] @ W2[q+1]
    gemm_kernel<float><<<dim3(N2 / BN, NROWS / BM), 256>>>(
        (const float*)p_h1, N1, H1W,
        W2 + (size_t)H1W * H2W, H2W, (long)H1W * H2W, H2W,
        (float*)p_t2, N2, H1W, 0);

    // H2 = relu(adj @ T2)
    gemm_kernel<__nv_bfloat16><<<dim3(N2 / BN, NROWS / BM), 256>>>(
        (const __nv_bfloat16*)p_adjb, NROWS, 0,
        (const float*)p_t2, N2, 0, N2,
        (float*)p_h2, N2, NROWS, 1);

    // column means + centering -> bf16 a slabs
    mean_kernel<<<N2 / 32, 256>>>((const float*)p_h2, (float*)p_mean);
    center_kernel<<<4096, 256>>>((const float*)p_h2, (const float*)p_mean,
                                 (__nv_bfloat16*)p_abf, (long)NROWS * N2);

    // fused sigmoid-accumulate output
    out_kernel<<<dim3(NROWS / BM, NROWS / BM), 256>>>(
        (const __nv_bfloat16*)p_abf, som, cum, tsp, Tp, out);
}

// round 3
// speedup vs baseline: 1.5460x; 1.5460x over previous
#include <cuda_runtime.h>
#include <cuda_bf16.h>
#include <mma.h>
#include <cstdint>

using namespace nvcuda;

// ---------------------------------------------------------------------------
// Problem shape
// ---------------------------------------------------------------------------
#define NROWS 8192
#define DIN   512
#define H1W   256
#define H2W   128
#define NSTEP 5
#define N1 (NSTEP*H1W)   // 1280
#define N2 (NSTEP*H2W)   // 640

// Staging: 128 rows x 64 bf16 per tile, smem row stride 72 elems (144B, LDSM
// conflict-free), 2 stages x (A+B)
#define KSTG  64
#define SLD   72
#define TILEB (128*SLD*2)      // 18432 bytes per tile
#define SMEMB (4*TILEB)        // 73728 total (epilogue Cs[128][129] f32 = 66048 overlays)
#define CLD   129

// ---------------------------------------------------------------------------
// Scratch (device globals — no runtime allocation allowed)
// ---------------------------------------------------------------------------
__device__ __nv_bfloat16 g_adjb[(size_t)NROWS*NROWS];
__device__ __nv_bfloat16 g_Xb  [(size_t)NROWS*DIN];
__device__ __nv_bfloat16 g_W1t [(size_t)NSTEP*H1W*DIN];   // [s][n][k]
__device__ __nv_bfloat16 g_W2t [(size_t)NSTEP*H2W*H1W];   // [s][n][k]
__device__ __nv_bfloat16 g_T1t [(size_t)N1*NROWS];        // (X@W1)^T  bf16
__device__ __nv_bfloat16 g_H1  [(size_t)NROWS*N1];        // relu(adj@T1) bf16
__device__ __nv_bfloat16 g_T2t [(size_t)N2*NROWS];        // (H1@W2)^T bf16
__device__ float         g_H2  [(size_t)NROWS*N2];        // relu(adj@T2) f32
__device__ __nv_bfloat16 g_abf [(size_t)NROWS*N2];        // centered a bf16
__device__ float         g_mean[N2];

// ---------------------------------------------------------------------------
// Helpers
// ---------------------------------------------------------------------------
static __device__ __forceinline__ uint32_t smem_u32(const void* p) {
    uint32_t a;
    asm("{ .reg .u64 t; cvta.to.shared.u64 t, %1; cvt.u32.u64 %0, t; }"
        : "=r"(a) : "l"(p));
    return a;
}
static __device__ __forceinline__ void cp16(uint32_t sdst, const void* g) {
    asm volatile("cp.async.cg.shared.global [%0], [%1], 16;"
                 :: "r"(sdst), "l"(g) : "memory");
}
static __device__ __forceinline__ void cp_commit() {
    asm volatile("cp.async.commit_group;" ::: "memory");
}
template <int N>
static __device__ __forceinline__ void cp_wait() {
    asm volatile("cp.async.wait_group %0;" :: "n"(N) : "memory");
}
static __device__ __forceinline__ void st4bf(__nv_bfloat16* p, float4 v) {
    __nv_bfloat162* q = reinterpret_cast<__nv_bfloat162*>(p);
    q[0] = __floats2bfloat162_rn(v.x, v.y);
    q[1] = __floats2bfloat162_rn(v.z, v.w);
}
static __device__ __forceinline__ float fast_sigmoid(float x) {
    float ax = fabsf(x);
    float x2 = x * x;
    float p = 0.5f + x * (0.25f + x2 * (-0.0208333333f + x2 * 0.00208333333f));
    unsigned vote = __ballot_sync(0xFFFFFFFFu, ax >= 0.25f);
    if (vote) {
        if (ax >= 0.25f) p = __fdividef(1.0f, 1.0f + __expf(-x));
    }
    return p;
}

// Stage one 128x64 bf16 tile into smem (row stride SLD) via cp.async.
// 1024 16B chunks, 4 per thread, fully coalesced.
static __device__ __forceinline__ void stage_tile(uint32_t sdst,
                                                  const __nv_bfloat16* __restrict__ src,
                                                  long ld) {
    const int t = threadIdx.x;
    #pragma unroll
    for (int i = 0; i < 4; i++) {
        int c = t + i * 256;
        int row = c >> 3, col = c & 7;
        cp16(sdst + row * (SLD * 2) + col * 16, src + (long)row * ld + col * 8);
    }
}

// MMA over one staged 64-K chunk: A tile (rows m), B tile (rows n, K-major ->
// col_major fragment). 8 warps: warp -> (wm = w>>1 in 0..3, wn = w&1 in 0..1).
template <typename FragC>
static __device__ __forceinline__ void mma_chunk(const __nv_bfloat16* As,
                                                 const __nv_bfloat16* Bs,
                                                 int wm, int wn, FragC (&cf)[2][4]) {
    #pragma unroll
    for (int kk = 0; kk < KSTG; kk += 16) {
        wmma::fragment<wmma::matrix_a, 16, 16, 16, __nv_bfloat16, wmma::row_major> af[2];
        wmma::fragment<wmma::matrix_b, 16, 16, 16, __nv_bfloat16, wmma::col_major> bf[4];
        #pragma unroll
        for (int i = 0; i < 2; i++)
            wmma::load_matrix_sync(af[i], As + (wm * 32 + i * 16) * SLD + kk, SLD);
        #pragma unroll
        for (int j = 0; j < 4; j++)
            wmma::load_matrix_sync(bf[j], Bs + (wn * 64 + j * 16) * SLD + kk, SLD);
        #pragma unroll
        for (int i = 0; i < 2; i++)
            #pragma unroll
            for (int j = 0; j < 4; j++)
                wmma::mma_sync(cf[i][j], af[i], bf[j], cf[i][j]);
    }
}

// ---------------------------------------------------------------------------
// Pipelined GEMM: C[M,N] = op(A[M,K] @ B[N,K]^T), bf16 K-major operands.
// EPI: 0 = bf16 transposed store, 1 = bf16 row-major + relu, 2 = f32 row + relu
// ---------------------------------------------------------------------------
template <int EPI>
__global__ void __launch_bounds__(256)
wgemm(const __nv_bfloat16* __restrict__ A, long lda, long aSlabCol,
      const __nv_bfloat16* __restrict__ B, long ldb, long bSlabStride, int outSlabN,
      char* __restrict__ Cv, long ldc, int K) {
    extern __shared__ char smem[];
    const uint32_t sb = smem_u32(smem);
    const int tid = threadIdx.x, warp = tid >> 5;
    const int wm = warp >> 1, wn = warp & 1;
    const int bx = blockIdx.x, by = blockIdx.y;

    const int slab = (bx * 128) / outSlabN;
    const __nv_bfloat16* Ab = A + (long)(by * 128) * lda + (long)slab * aSlabCol;
    const __nv_bfloat16* Bb = B + (long)slab * bSlabStride
                                + (long)((bx * 128) % outSlabN) * ldb;

    wmma::fragment<wmma::accumulator, 16, 16, 16, float> cf[2][4];
    #pragma unroll
    for (int i = 0; i < 2; i++)
        #pragma unroll
        for (int j = 0; j < 4; j++) wmma::fill_fragment(cf[i][j], 0.0f);

    const int KT = K >> 6;
    // prologue: stage 0
    stage_tile(sb, Ab, lda);
    stage_tile(sb + TILEB, Bb, ldb);
    cp_commit();

    for (int t = 0; t < KT; t++) {
        if (t + 1 < KT) {
            const uint32_t nb = sb + ((t + 1) & 1) * (2 * TILEB);
            stage_tile(nb, Ab + (long)(t + 1) * KSTG, lda);
            stage_tile(nb + TILEB, Bb + (long)(t + 1) * KSTG, ldb);
            cp_commit();
            cp_wait<1>();
        } else {
            cp_wait<0>();
        }
        __syncthreads();
        const char* buf = smem + (t & 1) * (2 * TILEB);
        mma_chunk((const __nv_bfloat16*)buf,
                  (const __nv_bfloat16*)(buf + TILEB), wm, wn, cf);
        __syncthreads();
    }

    // ---- epilogue ----
    if (EPI == 2) {
        #pragma unroll
        for (int i = 0; i < 2; i++)
            #pragma unroll
            for (int j = 0; j < 4; j++) {
                #pragma unroll
                for (int e = 0; e < cf[i][j].num_elements; e++)
                    cf[i][j].x[e] = fmaxf(cf[i][j].x[e], 0.0f);
                float* Cp = (float*)Cv + (long)(by * 128 + wm * 32 + i * 16) * ldc
                                       + (long)bx * 128 + wn * 64 + j * 16;
                wmma::store_matrix_sync(Cp, cf[i][j], ldc, wmma::mem_row_major);
            }
        return;
    }

    // bf16 outputs: route through smem Cs[128][129] f32
    float* Cs = (float*)smem;
    #pragma unroll
    for (int i = 0; i < 2; i++)
        #pragma unroll
        for (int j = 0; j < 4; j++)
            wmma::store_matrix_sync(Cs + (wm * 32 + i * 16) * CLD + wn * 64 + j * 16,
                                    cf[i][j], CLD, wmma::mem_row_major);
    __syncthreads();

    if (EPI == 0) {
        // transposed bf16: Ct[(bx*128+n)*ldc + by*128 + m]
        const int n = tid >> 1, mb = (tid & 1) * 64;
        uint32_t pk[32];
        #pragma unroll
        for (int k = 0; k < 32; k++) {
            __nv_bfloat162 h = __floats2bfloat162_rn(Cs[(mb + 2*k) * CLD + n],
                                                     Cs[(mb + 2*k + 1) * CLD + n]);
            pk[k] = *reinterpret_cast<uint32_t*>(&h);
        }
        __nv_bfloat16* dst = (__nv_bfloat16*)Cv + (long)(bx * 128 + n) * ldc
                                                + (long)by * 128 + mb;
        #pragma unroll
        for (int i = 0; i < 8; i++)
            reinterpret_cast<uint4*>(dst)[i] = *reinterpret_cast<uint4*>(pk + 4 * i);
    } else {
        // row-major bf16 + relu
        const int m = tid >> 1, nb = (tid & 1) * 64;
        uint32_t pk[32];
        #pragma unroll
        for (int k = 0; k < 32; k++) {
            float a = fmaxf(Cs[m * CLD + nb + 2*k],     0.0f);
            float b = fmaxf(Cs[m * CLD + nb + 2*k + 1], 0.0f);
            __nv_bfloat162 h = __floats2bfloat162_rn(a, b);
            pk[k] = *reinterpret_cast<uint32_t*>(&h);
        }
        __nv_bfloat16* dst = (__nv_bfloat16*)Cv + (long)(by * 128 + m) * ldc
                                                + (long)bx * 128 + nb;
        #pragma unroll
        for (int i = 0; i < 8; i++)
            reinterpret_cast<uint4*>(dst)[i] = *reinterpret_cast<uint4*>(pk + 4 * i);
    }
}

// ---------------------------------------------------------------------------
// Output kernel: symmetric (bx>=by only), per-step K=128 (2 staged chunks),
// sigmoid + coef accumulate, row store + mirrored col_major store.
// ---------------------------------------------------------------------------
__global__ void __launch_bounds__(256)
wout(const __nv_bfloat16* __restrict__ a,
     const float* __restrict__ som, const float* __restrict__ cum,
     const int* __restrict__ tsp, const int* __restrict__ Tp,
     float* __restrict__ out) {
    const int bx = blockIdx.x, by = blockIdx.y;
    if (bx < by) return;
    extern __shared__ char smem[];
    const uint32_t sb = smem_u32(smem);
    const int tid = threadIdx.x, warp = tid >> 5;
    const int wm = warp >> 1, wn = warp & 1;
    const int ts = *tsp, T = *Tp;

    wmma::fragment<wmma::accumulator, 16, 16, 16, float> of[2][4];
    #pragma unroll
    for (int i = 0; i < 2; i++)
        #pragma unroll
        for (int j = 0; j < 4; j++) wmma::fill_fragment(of[i][j], 0.0f);

    const __nv_bfloat16* Arow = a + (long)(by * 128) * N2;
    const __nv_bfloat16* Brow = a + (long)(bx * 128) * N2;

    for (int q = 0; q < NSTEP; q++) {
        if (q + 1 < ts || q + 1 > T) continue;
        // stage both 64-K chunks of this step for A(by) and B(bx)
        stage_tile(sb,             Arow + q * H2W,        N2);
        stage_tile(sb + TILEB,     Brow + q * H2W,        N2);
        cp_commit();
        stage_tile(sb + 2 * TILEB, Arow + q * H2W + KSTG, N2);
        stage_tile(sb + 3 * TILEB, Brow + q * H2W + KSTG, N2);
        cp_commit();

        wmma::fragment<wmma::accumulator, 16, 16, 16, float> cf[2][4];
        #pragma unroll
        for (int i = 0; i < 2; i++)
            #pragma unroll
            for (int j = 0; j < 4; j++) wmma::fill_fragment(cf[i][j], 0.0f);

        cp_wait<1>();
        __syncthreads();
        mma_chunk((const __nv_bfloat16*)smem,
                  (const __nv_bfloat16*)(smem + TILEB), wm, wn, cf);
        cp_wait<0>();
        __syncthreads();
        mma_chunk((const __nv_bfloat16*)(smem + 2 * TILEB),
                  (const __nv_bfloat16*)(smem + 3 * TILEB), wm, wn, cf);

        const float coef = som[q];
        #pragma unroll
        for (int i = 0; i < 2; i++)
            #pragma unroll
            for (int j = 0; j < 4; j++)
                #pragma unroll
                for (int e = 0; e < cf[i][j].num_elements; e++)
                    of[i][j].x[e] += coef * fast_sigmoid(cf[i][j].x[e]);
        __syncthreads();   // buffers reused next step
    }

    const float inv = __fdividef(1.0f, cum[ts - 1]);
    #pragma unroll
    for (int i = 0; i < 2; i++)
        #pragma unroll
        for (int j = 0; j < 4; j++) {
            #pragma unroll
            for (int e = 0; e < of[i][j].num_elements; e++)
                of[i][j].x[e] *= inv;
            const int mg = by * 128 + wm * 32 + i * 16;
            const int ng = bx * 128 + wn * 64 + j * 16;
            wmma::store_matrix_sync(out + (long)mg * NROWS + ng, of[i][j],
                                    NROWS, wmma::mem_row_major);
            if (bx != by)   // mirror: out[n][m] = v — free transpose via col_major
                wmma::store_matrix_sync(out + (long)ng * NROWS + mg, of[i][j],
                                        NROWS, wmma::mem_col_major);
        }
}

// ---------------------------------------------------------------------------
// Pre/post-processing
// ---------------------------------------------------------------------------
__global__ void cvt_bf16_kernel(const float* __restrict__ src,
                                __nv_bfloat16* __restrict__ dst, long n4) {
    long i = (long)blockIdx.x * blockDim.x + threadIdx.x;
    long stride = (long)gridDim.x * blockDim.x;
    for (; i < n4; i += stride) {
        float4 v = reinterpret_cast<const float4*>(src)[i];
        st4bf(dst + i * 4, v);
    }
}
__global__ void transpose_w_kernel(const float* __restrict__ W,
                                   __nv_bfloat16* __restrict__ Wt, int K, int N) {
    const int s = blockIdx.y;
    const float* Ws = W + (long)s * K * N;
    __nv_bfloat16* Wd = Wt + (long)s * K * N;
    for (int idx = blockIdx.x * blockDim.x + threadIdx.x; idx < K * N;
         idx += gridDim.x * blockDim.x) {
        int n = idx / K, k = idx % K;
        Wd[(long)n * K + k] = __float2bfloat16(Ws[(long)k * N + n]);
    }
}
__global__ void mean_kernel(const float* __restrict__ H2, float* __restrict__ mean) {
    const int tx = threadIdx.x & 31;
    const int ty = threadIdx.x >> 5;
    const int col = blockIdx.x * 32 + tx;
    float s = 0.0f;
    for (int r = ty; r < NROWS; r += 8)
        s += H2[(long)r * N2 + col];
    __shared__ float red[8][32];
    red[ty][tx] = s;
    __syncthreads();
    if (ty == 0) {
        float t = 0.0f;
        #pragma unroll
        for (int i = 0; i < 8; i++) t += red[i][tx];
        mean[col] = t * (1.0f / NROWS);
    }
}
__global__ void center_kernel(const float* __restrict__ H2,
                              const float* __restrict__ mean,
                              __nv_bfloat16* __restrict__ a, long n) {
    long i = (long)blockIdx.x * blockDim.x + threadIdx.x;
    long st = (long)gridDim.x * blockDim.x;
    for (; i < n; i += st) {
        int c = (int)(i % N2);
        a[i] = __float2bfloat16(H2[i] - mean[c]);
    }
}

// ---------------------------------------------------------------------------
// Launch
// ---------------------------------------------------------------------------
extern "C" void kernel_launch(void* const* d_in, const int* in_sizes, int n_in,
                              void* d_out, int out_size) {
    const float* X   = (const float*)d_in[0];
    const float* adj = (const float*)d_in[1];
    const float* W1  = (const float*)d_in[2];
    const float* W2  = (const float*)d_in[3];
    const float* cum = (const float*)d_in[4];
    const float* som = (const float*)d_in[5];
    const int*   tsp = (const int*)d_in[6];
    const int*   Tp  = (const int*)d_in[7];
    float* out = (float*)d_out;
    (void)in_sizes; (void)n_in; (void)out_size;

    void *p_adjb, *p_xb, *p_w1t, *p_w2t, *p_t1t, *p_h1, *p_t2t, *p_h2, *p_abf, *p_mean;
    cudaGetSymbolAddress(&p_adjb, g_adjb);
    cudaGetSymbolAddress(&p_xb,   g_Xb);
    cudaGetSymbolAddress(&p_w1t,  g_W1t);
    cudaGetSymbolAddress(&p_w2t,  g_W2t);
    cudaGetSymbolAddress(&p_t1t,  g_T1t);
    cudaGetSymbolAddress(&p_h1,   g_H1);
    cudaGetSymbolAddress(&p_t2t,  g_T2t);
    cudaGetSymbolAddress(&p_h2,   g_H2);
    cudaGetSymbolAddress(&p_abf,  g_abf);
    cudaGetSymbolAddress(&p_mean, g_mean);

    cudaFuncSetAttribute(wgemm<0>, cudaFuncAttributeMaxDynamicSharedMemorySize, SMEMB);
    cudaFuncSetAttribute(wgemm<1>, cudaFuncAttributeMaxDynamicSharedMemorySize, SMEMB);
    cudaFuncSetAttribute(wgemm<2>, cudaFuncAttributeMaxDynamicSharedMemorySize, SMEMB);
    cudaFuncSetAttribute(wout,     cudaFuncAttributeMaxDynamicSharedMemorySize, SMEMB);

    // conversions / transposes
    cvt_bf16_kernel<<<4096, 256>>>(adj, (__nv_bfloat16*)p_adjb, (long)NROWS * NROWS / 4);
    cvt_bf16_kernel<<<2048, 256>>>(X,   (__nv_bfloat16*)p_xb,   (long)NROWS * DIN / 4);
    transpose_w_kernel<<<dim3(64, NSTEP), 256>>>(W1 + (size_t)DIN * H1W,
                                                 (__nv_bfloat16*)p_w1t, DIN, H1W);
    transpose_w_kernel<<<dim3(32, NSTEP), 256>>>(W2 + (size_t)H1W * H2W,
                                                 (__nv_bfloat16*)p_w2t, H1W, H2W);

    // T1t = (X @ W1slab)^T          [1280 x 8192] bf16
    wgemm<0><<<dim3(N1/128, NROWS/128), 256, SMEMB>>>(
        (const __nv_bfloat16*)p_xb, DIN, 0,
        (const __nv_bfloat16*)p_w1t, DIN, (long)H1W * DIN, H1W,
        (char*)p_t1t, NROWS, DIN);

    // H1 = relu(adj @ T1)           [8192 x 1280] bf16
    wgemm<1><<<dim3(N1/128, NROWS/128), 256, SMEMB>>>(
        (const __nv_bfloat16*)p_adjb, NROWS, 0,
        (const __nv_bfloat16*)p_t1t, NROWS, 0, N1,
        (char*)p_h1, N1, NROWS);

    // T2t = (H1slab @ W2slab)^T     [640 x 8192] bf16
    wgemm<0><<<dim3(N2/128, NROWS/128), 256, SMEMB>>>(
        (const __nv_bfloat16*)p_h1, N1, H1W,
        (const __nv_bfloat16*)p_w2t, H1W, (long)H2W * H1W, H2W,
        (char*)p_t2t, NROWS, H1W);

    // H2 = relu(adj @ T2)           [8192 x 640] f32
    wgemm<2><<<dim3(N2/128, NROWS/128), 256, SMEMB>>>(
        (const __nv_bfloat16*)p_adjb, NROWS, 0,
        (const __nv_bfloat16*)p_t2t, NROWS, 0, N2,
        (char*)p_h2, N2, NROWS);

    mean_kernel<<<N2 / 32, 256>>>((const float*)p_h2, (float*)p_mean);
    center_kernel<<<4096, 256>>>((const float*)p_h2, (const float*)p_mean,
                                 (__nv_bfloat16*)p_abf, (long)NROWS * N2);

    wout<<<dim3(NROWS/128, NROWS/128), 256, SMEMB>>>(
        (const __nv_bfloat16*)p_abf, som, cum, tsp, Tp, out);
}